// round 15
// baseline (speedup 1.0000x reference)
#include <cuda_runtime.h>
#include <cuda_fp16.h>
#include <cstdint>

#define IN_F   4096
#define OUT_F  4096
#define TOKENS 8192

#define BM 128
#define BN 128
#define BK 64
#define NKI  (IN_F / BK)    // 64 iterations
#define KB16 (IN_F / 16)    // 256 k16-blocks along K

// fragment-major fp16 images: one 512B block per (16 x 16) tile, lane-major
__device__ __align__(16) uint8_t g_Ah[(size_t)TOKENS * IN_F * 2];  // 64 MB
__device__ __align__(16) uint8_t g_Bh[(size_t)OUT_F * IN_F * 2];   // 32 MB

#define NBLK_A ((TOKENS / 16) * KB16 * 32 / 256)   // 16384 prepass-A blocks
#define NBLK_B ((OUT_F / 16) * KB16 * 32 / 256)    // 8192  prepass-B blocks

__device__ __forceinline__ uint32_t smem_u32(const void* p) {
    return (uint32_t)__cvta_generic_to_shared(p);
}
__device__ __forceinline__ void cp16(uint32_t saddr, const void* g) {
    asm volatile("cp.async.cg.shared.global [%0], [%1], 16;\n" :: "r"(saddr), "l"(g));
}
__device__ __forceinline__ void lds128(uint4& v, uint32_t a) {
    asm volatile("ld.shared.v4.u32 {%0,%1,%2,%3}, [%4];"
                 : "=r"(v.x), "=r"(v.y), "=r"(v.z), "=r"(v.w) : "r"(a));
}
__device__ __forceinline__ void mma_f16(float* d, const uint4& a, uint32_t b0, uint32_t b1) {
    asm volatile("mma.sync.aligned.m16n8k16.row.col.f32.f16.f16.f32 "
                 "{%0,%1,%2,%3},{%4,%5,%6,%7},{%8,%9},{%0,%1,%2,%3};"
                 : "+f"(d[0]), "+f"(d[1]), "+f"(d[2]), "+f"(d[3])
                 : "r"(a.x), "r"(a.y), "r"(a.z), "r"(a.w), "r"(b0), "r"(b1));
}

// ---------------------------------------------------------------------------
// Fused prepass: blocks [0, NBLK_A) convert x -> fp16 A image (fragment-major);
// blocks [NBLK_A, NBLK_A+NBLK_B) dequant 4-bit -> fp16 B image.
// Running both halves in one launch overlaps their memory traffic.
// ---------------------------------------------------------------------------
__global__ void __launch_bounds__(256) prep_kernel(const float* __restrict__ x,
                                                   const int* __restrict__ qw,
                                                   const int* __restrict__ qz,
                                                   const float* __restrict__ scales) {
    if (blockIdx.x < NBLK_A) {
        int gid = blockIdx.x * 256 + threadIdx.x;
        int blk = gid >> 5, t = gid & 31;
        int m16 = blk >> 8;              // blk / KB16
        int k16 = blk & (KB16 - 1);
        int r = t >> 2, c = t & 3;
        const float* base = x + (size_t)(m16 * 16 + r) * IN_F + k16 * 16 + 2 * c;
        float2 v00 = *(const float2*)(base);
        float2 v01 = *(const float2*)(base + 8);
        float2 v10 = *(const float2*)(base + (size_t)8 * IN_F);
        float2 v11 = *(const float2*)(base + (size_t)8 * IN_F + 8);
        __half2 h0 = __floats2half2_rn(v00.x, v00.y);
        __half2 h1 = __floats2half2_rn(v10.x, v10.y);
        __half2 h2 = __floats2half2_rn(v01.x, v01.y);
        __half2 h3 = __floats2half2_rn(v11.x, v11.y);
        uint4 o;
        o.x = *(uint32_t*)&h0; o.y = *(uint32_t*)&h1;
        o.z = *(uint32_t*)&h2; o.w = *(uint32_t*)&h3;
        *(uint4*)(g_Ah + (size_t)blk * 512 + t * 16) = o;
    } else {
        int gid = (blockIdx.x - NBLK_A) * 256 + threadIdx.x;
        int blk = gid >> 5, t = gid & 31;
        int n16 = blk >> 8;              // blk / KB16
        int k16 = blk & (KB16 - 1);
        int c = t & 3;
        int k0 = k16 * 16;
        int g = k0 >> 7;
        int wrow = k0 >> 3;
        uint32_t o[4];
#pragma unroll
        for (int s_ = 0; s_ < 2; s_++) {
            int nu = n16 * 16 + (t >> 2) + s_ * 8;
            float sc = scales[g * OUT_F + nu];
            uint32_t zw = (uint32_t)qz[g * (OUT_F / 8) + (nu >> 3)];
            float nz = -sc * (float)(((zw >> ((nu & 7) * 4)) & 15u) + 1u);
            uint32_t w0 = (uint32_t)qw[(size_t)wrow * OUT_F + nu];
            uint32_t w1 = (uint32_t)qw[(size_t)(wrow + 1) * OUT_F + nu];
            float f0 = fmaf(sc, (float)((w0 >> (8 * c))     & 15u), nz);
            float f1 = fmaf(sc, (float)((w0 >> (8 * c + 4)) & 15u), nz);
            float f2 = fmaf(sc, (float)((w1 >> (8 * c))     & 15u), nz);
            float f3 = fmaf(sc, (float)((w1 >> (8 * c + 4)) & 15u), nz);
            __half2 b0 = __floats2half2_rn(f0, f1);
            __half2 b1 = __floats2half2_rn(f2, f3);
            o[s_ * 2]     = *(uint32_t*)&b0;
            o[s_ * 2 + 1] = *(uint32_t*)&b1;
        }
        uint4 v; v.x = o[0]; v.y = o[1]; v.z = o[2]; v.w = o[3];
        *(uint4*)(g_Bh + (size_t)blk * 512 + t * 16) = v;
    }
}

// ---------------------------------------------------------------------------
// GEMM: out = g_Ah @ g_Bh^T + bias.  CTA 128x128, 256 threads,
// warps 4(m) x 2(n), warp tile 32x64, BK=64 (4 k16 steps), 2-stage ring.
// 2 CTAs/SM: one CTA's barrier drain overlaps the other's mma stream.
// ---------------------------------------------------------------------------
#define STG 32768                       // stage: A 16KB + B 16KB
#define SMEM_TOTAL (2 * STG)            // 65536 per CTA

__global__ void __launch_bounds__(256, 2)
gemm_kernel(const float* __restrict__ bias, float* __restrict__ out) {
    extern __shared__ __align__(16) char smem[];
    const uint32_t sb = smem_u32(smem);
    const int tid  = threadIdx.x;
    const int wid  = tid >> 5;
    const int lane = tid & 31;
    const int wm   = wid & 3;           // m-warp 0..3
    const int wn   = wid >> 2;          // n-warp 0..1
    const int m0   = blockIdx.y * BM;
    const int n0   = blockIdx.x * BN;

    float acc[2][8][4];
#pragma unroll
    for (int mi = 0; mi < 2; mi++)
#pragma unroll
        for (int ni = 0; ni < 8; ni++)
#pragma unroll
            for (int j = 0; j < 4; j++) acc[mi][ni][j] = 0.0f;

    // fill: A 8 m16-blk x 4 k16-blk (1024 chunks), B 8 n16-blk x 4 (1024 chunks)
    auto fill = [&](int it) {
        uint32_t st = sb + (uint32_t)(it & 1) * STG;
        int kb = it * 4;
#pragma unroll
        for (int j = 0; j < 4; j++) {
            int c2 = tid + 256 * j;
            int blk = c2 >> 5, ln = c2 & 31;
            int mblk = blk >> 2, kblk = blk & 3;
            const uint8_t* src = g_Ah +
                ((size_t)((m0 >> 4) + mblk) * KB16 + kb + kblk) * 512 + ln * 16;
            cp16(st + (uint32_t)blk * 512 + ln * 16, src);
        }
#pragma unroll
        for (int j = 0; j < 4; j++) {
            int c2 = tid + 256 * j;
            int blk = c2 >> 5, ln = c2 & 31;
            int nblk = blk >> 2, kblk = blk & 3;
            const uint8_t* src = g_Bh +
                ((size_t)((n0 >> 4) + nblk) * KB16 + kb + kblk) * 512 + ln * 16;
            cp16(st + 16384 + (uint32_t)blk * 512 + ln * 16, src);
        }
    };

    fill(0);
    asm volatile("cp.async.commit_group;\n" ::: "memory");

    const uint32_t f_off = (uint32_t)lane * 16;

    for (int it = 0; it < NKI; it++) {
        asm volatile("cp.async.wait_group 0;\n" ::: "memory");
        __syncthreads();
        if (it + 1 < NKI) {
            fill(it + 1);
            asm volatile("cp.async.commit_group;\n" ::: "memory");
        }

        const uint32_t st = sb + (uint32_t)(it & 1) * STG;
#pragma unroll
        for (int ks = 0; ks < 4; ks++) {
            uint4 a[2], b[4];
#pragma unroll
            for (int mi = 0; mi < 2; mi++)
                lds128(a[mi], st + (uint32_t)(((wm * 2 + mi) * 4 + ks)) * 512 + f_off);
#pragma unroll
            for (int np = 0; np < 4; np++)
                lds128(b[np], st + 16384 + (uint32_t)(((wn * 4 + np) * 4 + ks)) * 512 + f_off);
#pragma unroll
            for (int mi = 0; mi < 2; mi++)
#pragma unroll
                for (int np = 0; np < 4; np++) {
                    mma_f16(acc[mi][np * 2],     a[mi], b[np].x, b[np].y);
                    mma_f16(acc[mi][np * 2 + 1], a[mi], b[np].z, b[np].w);
                }
        }
    }

    // epilogue: + bias
#pragma unroll
    for (int mi = 0; mi < 2; mi++) {
        int r0 = m0 + wm * 32 + mi * 16 + (lane >> 2);
#pragma unroll
        for (int np = 0; np < 4; np++)
#pragma unroll
            for (int sub = 0; sub < 2; sub++) {
                int c = n0 + wn * 64 + np * 16 + sub * 8 + (lane & 3) * 2;
                const float* d = acc[mi][np * 2 + sub];
                float2 bv = *(const float2*)(bias + c);
                float2 v0, v1;
                v0.x = d[0] + bv.x; v0.y = d[1] + bv.y;
                v1.x = d[2] + bv.x; v1.y = d[3] + bv.y;
                *(float2*)(out + (size_t)r0 * OUT_F + c)       = v0;
                *(float2*)(out + (size_t)(r0 + 8) * OUT_F + c) = v1;
            }
    }
}

// ---------------------------------------------------------------------------
// Launch.  inputs: x, qweight, qzeros, scales, g_idx, bias
// ---------------------------------------------------------------------------
extern "C" void kernel_launch(void* const* d_in, const int* in_sizes, int n_in,
                              void* d_out, int out_size) {
    const float* x       = (const float*)d_in[0];
    const int*   qweight = (const int*)d_in[1];
    const int*   qzeros  = (const int*)d_in[2];
    const float* scales  = (const float*)d_in[3];
    const float* bias    = (const float*)d_in[5];
    float*       out     = (float*)d_out;

    prep_kernel<<<NBLK_A + NBLK_B, 256>>>(x, qweight, qzeros, scales);

    cudaFuncSetAttribute(gemm_kernel, cudaFuncAttributeMaxDynamicSharedMemorySize,
                         SMEM_TOTAL);
    dim3 grid(OUT_F / BN, TOKENS / BM);
    gemm_kernel<<<grid, 256, SMEM_TOTAL>>>(bias, out);
}

// round 16
// speedup vs baseline: 1.0149x; 1.0149x over previous
#include <cuda_runtime.h>
#include <cuda_fp16.h>
#include <cstdint>

#define IN_F   4096
#define OUT_F  4096
#define TOKENS 8192

#define BM 128
#define BN 128
#define BK 64
#define NKI  (IN_F / BK)    // 64 iterations
#define KB16 (IN_F / 16)    // 256 k16-blocks along K

// fragment-major fp16 images: one 512B block per (16 x 16) tile, lane-major
__device__ __align__(16) uint8_t g_Ah[(size_t)TOKENS * IN_F * 2];  // 64 MB
__device__ __align__(16) uint8_t g_Bh[(size_t)OUT_F * IN_F * 2];   // 32 MB

#define NBLK_A ((TOKENS / 16) * KB16 * 32 / 256)   // 16384 prepass-A blocks
#define NBLK_B ((OUT_F / 16) * KB16 * 32 / 256)    // 8192  prepass-B blocks

__device__ __forceinline__ uint32_t smem_u32(const void* p) {
    return (uint32_t)__cvta_generic_to_shared(p);
}
__device__ __forceinline__ void cp16(uint32_t saddr, const void* g) {
    asm volatile("cp.async.cg.shared.global [%0], [%1], 16;\n" :: "r"(saddr), "l"(g));
}
__device__ __forceinline__ void lds128(uint4& v, uint32_t a) {
    asm volatile("ld.shared.v4.u32 {%0,%1,%2,%3}, [%4];"
                 : "=r"(v.x), "=r"(v.y), "=r"(v.z), "=r"(v.w) : "r"(a));
}
__device__ __forceinline__ void mma_f16(float* d, const uint4& a, uint32_t b0, uint32_t b1) {
    asm volatile("mma.sync.aligned.m16n8k16.row.col.f32.f16.f16.f32 "
                 "{%0,%1,%2,%3},{%4,%5,%6,%7},{%8,%9},{%0,%1,%2,%3};"
                 : "+f"(d[0]), "+f"(d[1]), "+f"(d[2]), "+f"(d[3])
                 : "r"(a.x), "r"(a.y), "r"(a.z), "r"(a.w), "r"(b0), "r"(b1));
}

// ---------------------------------------------------------------------------
// Fused prepass: blocks [0, NBLK_A) convert x -> fp16 A image (fragment-major);
// blocks [NBLK_A, NBLK_A+NBLK_B) dequant 4-bit -> fp16 B image.
// ---------------------------------------------------------------------------
__global__ void __launch_bounds__(256) prep_kernel(const float* __restrict__ x,
                                                   const int* __restrict__ qw,
                                                   const int* __restrict__ qz,
                                                   const float* __restrict__ scales) {
    if (blockIdx.x < NBLK_A) {
        int gid = blockIdx.x * 256 + threadIdx.x;
        int blk = gid >> 5, t = gid & 31;
        int m16 = blk >> 8;              // blk / KB16
        int k16 = blk & (KB16 - 1);
        int r = t >> 2, c = t & 3;
        const float* base = x + (size_t)(m16 * 16 + r) * IN_F + k16 * 16 + 2 * c;
        float2 v00 = *(const float2*)(base);
        float2 v01 = *(const float2*)(base + 8);
        float2 v10 = *(const float2*)(base + (size_t)8 * IN_F);
        float2 v11 = *(const float2*)(base + (size_t)8 * IN_F + 8);
        __half2 h0 = __floats2half2_rn(v00.x, v00.y);
        __half2 h1 = __floats2half2_rn(v10.x, v10.y);
        __half2 h2 = __floats2half2_rn(v01.x, v01.y);
        __half2 h3 = __floats2half2_rn(v11.x, v11.y);
        uint4 o;
        o.x = *(uint32_t*)&h0; o.y = *(uint32_t*)&h1;
        o.z = *(uint32_t*)&h2; o.w = *(uint32_t*)&h3;
        *(uint4*)(g_Ah + (size_t)blk * 512 + t * 16) = o;
    } else {
        int gid = (blockIdx.x - NBLK_A) * 256 + threadIdx.x;
        int blk = gid >> 5, t = gid & 31;
        int n16 = blk >> 8;              // blk / KB16
        int k16 = blk & (KB16 - 1);
        int c = t & 3;
        int k0 = k16 * 16;
        int g = k0 >> 7;
        int wrow = k0 >> 3;
        uint32_t o[4];
#pragma unroll
        for (int s_ = 0; s_ < 2; s_++) {
            int nu = n16 * 16 + (t >> 2) + s_ * 8;
            float sc = scales[g * OUT_F + nu];
            uint32_t zw = (uint32_t)qz[g * (OUT_F / 8) + (nu >> 3)];
            float nz = -sc * (float)(((zw >> ((nu & 7) * 4)) & 15u) + 1u);
            uint32_t w0 = (uint32_t)qw[(size_t)wrow * OUT_F + nu];
            uint32_t w1 = (uint32_t)qw[(size_t)(wrow + 1) * OUT_F + nu];
            float f0 = fmaf(sc, (float)((w0 >> (8 * c))     & 15u), nz);
            float f1 = fmaf(sc, (float)((w0 >> (8 * c + 4)) & 15u), nz);
            float f2 = fmaf(sc, (float)((w1 >> (8 * c))     & 15u), nz);
            float f3 = fmaf(sc, (float)((w1 >> (8 * c + 4)) & 15u), nz);
            __half2 b0 = __floats2half2_rn(f0, f1);
            __half2 b1 = __floats2half2_rn(f2, f3);
            o[s_ * 2]     = *(uint32_t*)&b0;
            o[s_ * 2 + 1] = *(uint32_t*)&b1;
        }
        uint4 v; v.x = o[0]; v.y = o[1]; v.z = o[2]; v.w = o[3];
        *(uint4*)(g_Bh + (size_t)blk * 512 + t * 16) = v;
    }
}

// ---------------------------------------------------------------------------
// GEMM: out = g_Ah @ g_Bh^T + bias.  CTA 128x128, 256 threads,
// warps 4(m) x 2(n), warp tile 32x64, BK=64 (4 k16 steps), 3-stage ring,
// wait_group 1 (each fill gets 2 iterations to land).  2 CTAs/SM.
// ---------------------------------------------------------------------------
#define STG 32768                       // stage: A 16KB + B 16KB
#define SMEM_TOTAL (3 * STG)            // 98304 per CTA, 2 CTAs = 192KB/SM

__global__ void __launch_bounds__(256, 2)
gemm_kernel(const float* __restrict__ bias, float* __restrict__ out) {
    extern __shared__ __align__(16) char smem[];
    const uint32_t sb = smem_u32(smem);
    const int tid  = threadIdx.x;
    const int wid  = tid >> 5;
    const int lane = tid & 31;
    const int wm   = wid & 3;           // m-warp 0..3
    const int wn   = wid >> 2;          // n-warp 0..1
    const int m0   = blockIdx.y * BM;
    const int n0   = blockIdx.x * BN;

    float acc[2][8][4];
#pragma unroll
    for (int mi = 0; mi < 2; mi++)
#pragma unroll
        for (int ni = 0; ni < 8; ni++)
#pragma unroll
            for (int j = 0; j < 4; j++) acc[mi][ni][j] = 0.0f;

    // fill: A 8 m16-blk x 4 k16-blk (1024 chunks), B 8 n16-blk x 4 (1024 chunks)
    auto fill = [&](int it) {
        uint32_t st = sb + (uint32_t)(it % 3) * STG;
        int kb = it * 4;
#pragma unroll
        for (int j = 0; j < 4; j++) {
            int c2 = tid + 256 * j;
            int blk = c2 >> 5, ln = c2 & 31;
            int mblk = blk >> 2, kblk = blk & 3;
            const uint8_t* src = g_Ah +
                ((size_t)((m0 >> 4) + mblk) * KB16 + kb + kblk) * 512 + ln * 16;
            cp16(st + (uint32_t)blk * 512 + ln * 16, src);
        }
#pragma unroll
        for (int j = 0; j < 4; j++) {
            int c2 = tid + 256 * j;
            int blk = c2 >> 5, ln = c2 & 31;
            int nblk = blk >> 2, kblk = blk & 3;
            const uint8_t* src = g_Bh +
                ((size_t)((n0 >> 4) + nblk) * KB16 + kb + kblk) * 512 + ln * 16;
            cp16(st + 16384 + (uint32_t)blk * 512 + ln * 16, src);
        }
    };

    fill(0);
    asm volatile("cp.async.commit_group;\n" ::: "memory");
    fill(1);
    asm volatile("cp.async.commit_group;\n" ::: "memory");

    const uint32_t f_off = (uint32_t)lane * 16;

    for (int it = 0; it < NKI; it++) {
        asm volatile("cp.async.wait_group 1;\n" ::: "memory");
        __syncthreads();
        if (it + 2 < NKI) {
            fill(it + 2);
            asm volatile("cp.async.commit_group;\n" ::: "memory");
        }

        const uint32_t st = sb + (uint32_t)(it % 3) * STG;
#pragma unroll
        for (int ks = 0; ks < 4; ks++) {
            uint4 a[2], b[4];
#pragma unroll
            for (int mi = 0; mi < 2; mi++)
                lds128(a[mi], st + (uint32_t)(((wm * 2 + mi) * 4 + ks)) * 512 + f_off);
#pragma unroll
            for (int np = 0; np < 4; np++)
                lds128(b[np], st + 16384 + (uint32_t)(((wn * 4 + np) * 4 + ks)) * 512 + f_off);
#pragma unroll
            for (int mi = 0; mi < 2; mi++)
#pragma unroll
                for (int np = 0; np < 4; np++) {
                    mma_f16(acc[mi][np * 2],     a[mi], b[np].x, b[np].y);
                    mma_f16(acc[mi][np * 2 + 1], a[mi], b[np].z, b[np].w);
                }
        }
    }

    // epilogue: + bias
#pragma unroll
    for (int mi = 0; mi < 2; mi++) {
        int r0 = m0 + wm * 32 + mi * 16 + (lane >> 2);
#pragma unroll
        for (int np = 0; np < 4; np++)
#pragma unroll
            for (int sub = 0; sub < 2; sub++) {
                int c = n0 + wn * 64 + np * 16 + sub * 8 + (lane & 3) * 2;
                const float* d = acc[mi][np * 2 + sub];
                float2 bv = *(const float2*)(bias + c);
                float2 v0, v1;
                v0.x = d[0] + bv.x; v0.y = d[1] + bv.y;
                v1.x = d[2] + bv.x; v1.y = d[3] + bv.y;
                *(float2*)(out + (size_t)r0 * OUT_F + c)       = v0;
                *(float2*)(out + (size_t)(r0 + 8) * OUT_F + c) = v1;
            }
    }
}

// ---------------------------------------------------------------------------
// Launch.  inputs: x, qweight, qzeros, scales, g_idx, bias
// ---------------------------------------------------------------------------
extern "C" void kernel_launch(void* const* d_in, const int* in_sizes, int n_in,
                              void* d_out, int out_size) {
    const float* x       = (const float*)d_in[0];
    const int*   qweight = (const int*)d_in[1];
    const int*   qzeros  = (const int*)d_in[2];
    const float* scales  = (const float*)d_in[3];
    const float* bias    = (const float*)d_in[5];
    float*       out     = (float*)d_out;

    prep_kernel<<<NBLK_A + NBLK_B, 256>>>(x, qweight, qzeros, scales);

    cudaFuncSetAttribute(gemm_kernel, cudaFuncAttributeMaxDynamicSharedMemorySize,
                         SMEM_TOTAL);
    dim3 grid(OUT_F / BN, TOKENS / BM);
    gemm_kernel<<<grid, 256, SMEM_TOTAL>>>(bias, out);
}